// round 1
// baseline (speedup 1.0000x reference)
#include <cuda_runtime.h>

#define TOK   49
#define NH    12
#define DM    384
#define HD    32
#define NWIN  4096
#define MT    (NWIN * TOK)     /* 200704 rows */
#define QKVN  (3 * DM)         /* 1152 */

// ---------------- scratch (device globals: allocation-guard safe) ----------------
__device__ float g_qkv[MT * QKVN];      // 231,211,008 floats (~925 MB)
__device__ float g_att[MT * DM];        //  77,070,336 floats (~308 MB)
__device__ float g_bias[NH * TOK * TOK]; // 28,812 floats

// ---------------- bias expand: bx[h,i,j] = table[rel_index[i,j], h] ----------------
__global__ void bias_expand(const float* __restrict__ bt, const int* __restrict__ ri,
                            float* __restrict__ bx)
{
    int idx = blockIdx.x * blockDim.x + threadIdx.x;
    if (idx < NH * TOK * TOK) {
        int h  = idx / (TOK * TOK);
        int ij = idx % (TOK * TOK);
        bx[idx] = bt[ri[ij] * NH + h];
    }
}

// ---------------- SGEMM: C[m,n] = sum_k A[m,k]*B[n,k] + bias[n] ----------------
// A: (M,K) row-major, B: (N,K) row-major (both K-contiguous -> NT gemm).
// Exact tiles: M % 128 == 0, N % 128 == 0, K % 8 == 0 (no bounds checks).
// 128x128 block tile, BK=8, 256 threads, 8x8 per-thread register tile.
__global__ __launch_bounds__(256, 2)
void sgemm_nt_bias(const float* __restrict__ A, const float* __restrict__ B,
                   const float* __restrict__ bias, float* __restrict__ C,
                   int N, int K)
{
    __shared__ float As[8][128];
    __shared__ float Bs[8][128];

    const int tid = threadIdx.x;
    const int tx  = tid & 15;        // 16 col-threads
    const int ty  = tid >> 4;        // 16 row-threads
    const int m0  = blockIdx.y << 7;
    const int n0  = blockIdx.x << 7;

    // gmem load mapping: each thread loads one float4 of A and one of B per k-tile
    const int lr = tid >> 1;          // 0..127 (row within tile)
    const int lk = (tid & 1) << 2;    // 0 or 4 (k offset)

    const float* Ag = A + (size_t)(m0 + lr) * K + lk;
    const float* Bg = B + (size_t)(n0 + lr) * K + lk;

    float4 ar = *(const float4*)Ag;
    float4 br = *(const float4*)Bg;

    float acc[8][8];
#pragma unroll
    for (int i = 0; i < 8; ++i)
#pragma unroll
        for (int j = 0; j < 8; ++j) acc[i][j] = 0.f;

    const int nk = K >> 3;
    for (int kt = 0; kt < nk; ++kt) {
        // store current tile (transposed: As[k][m]) so compute reads are float4
        As[lk + 0][lr] = ar.x; As[lk + 1][lr] = ar.y;
        As[lk + 2][lr] = ar.z; As[lk + 3][lr] = ar.w;
        Bs[lk + 0][lr] = br.x; Bs[lk + 1][lr] = br.y;
        Bs[lk + 2][lr] = br.z; Bs[lk + 3][lr] = br.w;
        __syncthreads();

        if (kt + 1 < nk) {  // prefetch next tile into registers, overlapping compute
            ar = *(const float4*)(Ag + (size_t)(kt + 1) * 8);
            br = *(const float4*)(Bg + (size_t)(kt + 1) * 8);
        }

#pragma unroll
        for (int kk = 0; kk < 8; ++kk) {
            float a[8], b[8];
            *(float4*)&a[0] = *(const float4*)&As[kk][ty * 8];
            *(float4*)&a[4] = *(const float4*)&As[kk][ty * 8 + 4];
            *(float4*)&b[0] = *(const float4*)&Bs[kk][tx * 8];
            *(float4*)&b[4] = *(const float4*)&Bs[kk][tx * 8 + 4];
#pragma unroll
            for (int i = 0; i < 8; ++i)
#pragma unroll
                for (int j = 0; j < 8; ++j)
                    acc[i][j] += a[i] * b[j];
        }
        __syncthreads();
    }

    float bv[8];
#pragma unroll
    for (int j = 0; j < 8; ++j) bv[j] = bias[n0 + tx * 8 + j];

#pragma unroll
    for (int i = 0; i < 8; ++i) {
        float* Cp = C + (size_t)(m0 + ty * 8 + i) * N + (n0 + tx * 8);
        float4 o;
        o.x = acc[i][0] + bv[0]; o.y = acc[i][1] + bv[1];
        o.z = acc[i][2] + bv[2]; o.w = acc[i][3] + bv[3];
        *(float4*)Cp = o;
        o.x = acc[i][4] + bv[4]; o.y = acc[i][5] + bv[5];
        o.z = acc[i][6] + bv[6]; o.w = acc[i][7] + bv[7];
        *(float4*)(Cp + 4) = o;
    }
}

// ---------------- windowed attention: one block per (window b, head h) ----------------
// S = (q*scale) k^T + bias[h]; P = softmax(S); out[b, i, h*32+d] = sum_j P[i,j] v[j,d]
__global__ __launch_bounds__(192)
void attn_kernel(const float* __restrict__ qkv, const float* __restrict__ bx,
                 float* __restrict__ out)
{
    const int h   = blockIdx.x;
    const int b   = blockIdx.y;
    const int tid = threadIdx.x;

    __shared__ float qt[32][52];   // qt[d][i], cols 49..51 zero-padded
    __shared__ float kt[32][52];   // kt[d][j], cols 49..51 zero-padded
    __shared__ float vs[49][32];   // v[j][d]
    __shared__ float Ps[52][53];   // S / P, rows 49..51 zero

    const size_t base = (size_t)b * TOK * QKVN + (size_t)h * HD;

    // zero the pad columns of qt/kt (32 d-rows x 3 pad cols)
    if (tid < 96) {
        int d = tid / 3, c = 49 + tid % 3;
        qt[d][c] = 0.f; kt[d][c] = 0.f;
    }
    // load q,k (transposed) and v: 49 tokens x 8 float4 = 392 vector loads each
    for (int e = tid; e < 392; e += 192) {
        int n = e >> 3, d4 = (e & 7) << 2;
        const float* p = qkv + base + (size_t)n * QKVN + d4;
        float4 q4 = *(const float4*)(p);
        float4 k4 = *(const float4*)(p + DM);
        float4 v4 = *(const float4*)(p + 2 * DM);
        qt[d4 + 0][n] = q4.x; qt[d4 + 1][n] = q4.y;
        qt[d4 + 2][n] = q4.z; qt[d4 + 3][n] = q4.w;
        kt[d4 + 0][n] = k4.x; kt[d4 + 1][n] = k4.y;
        kt[d4 + 2][n] = k4.z; kt[d4 + 3][n] = k4.w;
        *(float4*)&vs[n][d4] = v4;
    }
    __syncthreads();

    // ---- S = q k^T : 13x13 thread grid, 4x4 register tile each ----
    if (tid < 169) {
        const int ti = tid % 13, tj = tid / 13;
        const int i0 = ti * 4, j0 = tj * 4;
        float acc[4][4] = {};
#pragma unroll 8
        for (int d = 0; d < 32; ++d) {
            float4 a = *(const float4*)&qt[d][i0];
            float4 c = *(const float4*)&kt[d][j0];
            float av[4] = {a.x, a.y, a.z, a.w};
            float cv[4] = {c.x, c.y, c.z, c.w};
#pragma unroll
            for (int r = 0; r < 4; ++r)
#pragma unroll
                for (int s = 0; s < 4; ++s) acc[r][s] += av[r] * cv[s];
        }
        const float scale = 0.17677669529663687f;  // 32^-0.5
        const float* bh = bx + h * (TOK * TOK);
#pragma unroll
        for (int r = 0; r < 4; ++r)
#pragma unroll
            for (int s = 0; s < 4; ++s) {
                int i = i0 + r, j = j0 + s;
                float v = 0.f;
                if (i < TOK && j < TOK) v = acc[r][s] * scale + bh[i * TOK + j];
                Ps[i][j] = v;
            }
    }
    __syncthreads();

    // ---- softmax per row (rows 0..48) ----
    if (tid < TOK) {
        float mx = -1e30f;
        for (int j = 0; j < TOK; ++j) mx = fmaxf(mx, Ps[tid][j]);
        float s = 0.f;
        for (int j = 0; j < TOK; ++j) {
            float e = __expf(Ps[tid][j] - mx);
            Ps[tid][j] = e; s += e;
        }
        float inv = 1.f / s;
        for (int j = 0; j < TOK; ++j) Ps[tid][j] *= inv;
    }
    __syncthreads();

    // ---- out = P v : 13(i) x 8(d4) thread grid, 4x4 register tile ----
    if (tid < 104) {
        const int ti = tid % 13, td = tid / 13;
        const int i0 = ti * 4, d0 = td * 4;
        float acc[4][4] = {};
        for (int j = 0; j < TOK; ++j) {
            float4 vv = *(const float4*)&vs[j][d0];
            float p0 = Ps[i0 + 0][j], p1 = Ps[i0 + 1][j];
            float p2 = Ps[i0 + 2][j], p3 = Ps[i0 + 3][j];
            acc[0][0] += p0 * vv.x; acc[0][1] += p0 * vv.y; acc[0][2] += p0 * vv.z; acc[0][3] += p0 * vv.w;
            acc[1][0] += p1 * vv.x; acc[1][1] += p1 * vv.y; acc[1][2] += p1 * vv.z; acc[1][3] += p1 * vv.w;
            acc[2][0] += p2 * vv.x; acc[2][1] += p2 * vv.y; acc[2][2] += p2 * vv.z; acc[2][3] += p2 * vv.w;
            acc[3][0] += p3 * vv.x; acc[3][1] += p3 * vv.y; acc[3][2] += p3 * vv.z; acc[3][3] += p3 * vv.w;
        }
#pragma unroll
        for (int r = 0; r < 4; ++r) {
            int i = i0 + r;
            if (i < TOK) {
                float4 o = {acc[r][0], acc[r][1], acc[r][2], acc[r][3]};
                *(float4*)(out + ((size_t)b * TOK + i) * DM + h * HD + d0) = o;
            }
        }
    }
}

// ---------------- launch ----------------
extern "C" void kernel_launch(void* const* d_in, const int* in_sizes, int n_in,
                              void* d_out, int out_size)
{
    const float* x  = (const float*)d_in[0];
    const float* qw = (const float*)d_in[1];
    const float* qb = (const float*)d_in[2];
    const float* pw = (const float*)d_in[3];
    const float* pb = (const float*)d_in[4];
    const float* bt = (const float*)d_in[5];
    const int*   ri = (const int*)d_in[6];
    float* out = (float*)d_out;

    float *qkv, *att, *bx;
    cudaGetSymbolAddress((void**)&qkv, g_qkv);
    cudaGetSymbolAddress((void**)&att, g_att);
    cudaGetSymbolAddress((void**)&bx,  g_bias);

    // 1) expand relative-position bias to (H, 49, 49)
    bias_expand<<<(NH * TOK * TOK + 255) / 256, 256>>>(bt, ri, bx);

    // 2) QKV projection: (200704,384) x (1152,384)^T -> (200704,1152)
    sgemm_nt_bias<<<dim3(QKVN / 128, MT / 128), 256>>>(x, qw, qb, qkv, QKVN, DM);

    // 3) windowed attention per (head, window)
    attn_kernel<<<dim3(NH, NWIN), 192>>>(qkv, bx, att);

    // 4) output projection: (200704,384) x (384,384)^T -> d_out
    sgemm_nt_bias<<<dim3(DM / 128, MT / 128), 256>>>(att, pw, pb, out, DM, DM);
}

// round 2
// speedup vs baseline: 2.0053x; 2.0053x over previous
#include <cuda_runtime.h>
#include <cstdint>

#define TOK   49
#define NH    12
#define DM    384
#define HD    32
#define NWIN  4096
#define MT    (NWIN * TOK)     /* 200704 rows */
#define QKVN  (3 * DM)         /* 1152 */

// ---------------- scratch (device globals: allocation-guard safe) ----------------
__device__ float g_qkv[MT * QKVN];       // ~925 MB
__device__ float g_att[MT * DM];         // ~308 MB
__device__ float g_bias[NH * TOK * TOK]; // 28,812 floats

// ---------------- bias expand: bx[h,i,j] = table[rel_index[i,j], h] ----------------
__global__ void bias_expand(const float* __restrict__ bt, const int* __restrict__ ri,
                            float* __restrict__ bx)
{
    int idx = blockIdx.x * blockDim.x + threadIdx.x;
    if (idx < NH * TOK * TOK) {
        int h  = idx / (TOK * TOK);
        int ij = idx % (TOK * TOK);
        bx[idx] = bt[ri[ij] * NH + h];
    }
}

// ---------------- helpers ----------------
__device__ __forceinline__ uint32_t f2tf32(float f) {
    uint32_t u;
    asm("cvt.rna.tf32.f32 %0, %1;" : "=r"(u) : "f"(f));
    return u;
}

__device__ __forceinline__ void mma_tf32(float c[4], const uint32_t a[4], const uint32_t b[2]) {
    asm volatile(
        "mma.sync.aligned.m16n8k8.row.col.f32.tf32.tf32.f32 "
        "{%0,%1,%2,%3}, {%4,%5,%6,%7}, {%8,%9}, {%0,%1,%2,%3};"
        : "+f"(c[0]), "+f"(c[1]), "+f"(c[2]), "+f"(c[3])
        : "r"(a[0]), "r"(a[1]), "r"(a[2]), "r"(a[3]), "r"(b[0]), "r"(b[1]));
}

// ---------------- TF32 tensor-core GEMM: C[m,n] = sum_k A[m,k]*B[n,k] + bias[n] ----------------
// A: (M,K) row-major, B: (N,K) row-major ("row.col" mma: B[n][k] IS col-major k x n).
// Exact tiles: M % 128 == 0, N % 128 == 0, K % 16 == 0.
// 128x128 block tile, BK=16, 256 threads (8 warps), warp tile 64x32, m16n8k8 sub-tiles.
__global__ __launch_bounds__(256)
void gemm_tf32_nt_bias(const float* __restrict__ A, const float* __restrict__ B,
                       const float* __restrict__ bias, float* __restrict__ C,
                       int N, int K)
{
    // stride 20 (not 16): banks (20*r + c) % 32 are distinct for 8 consecutive rows
    // across the 4-col fragment groups -> conflict-free fragment LDS.
    __shared__ uint32_t As[128][20];
    __shared__ uint32_t Bs[128][20];

    const int tid  = threadIdx.x;
    const int m0   = blockIdx.y << 7;
    const int n0   = blockIdx.x << 7;
    const int lane = tid & 31;
    const int warp = tid >> 5;
    const int wm   = (warp & 1) << 6;   // warp M offset: 0 / 64
    const int wn   = (warp >> 1) << 5;  // warp N offset: 0 / 32 / 64 / 96
    const int qr   = lane >> 2;         // 0..7
    const int qc   = lane & 3;          // 0..3

    // gmem loader: 512 float4 per 128x16 tile; thread t loads #t and #(t+256)
    const int lr = tid >> 2;            // rows 0..63 (and +64)
    const int lc = (tid & 3) << 2;      // col offset 0/4/8/12

    const float* Ag = A + (size_t)(m0 + lr) * K + lc;
    const float* Bg = B + (size_t)(n0 + lr) * K + lc;
    const size_t off64 = (size_t)64 * K;

    float4 pa0 = *(const float4*)(Ag);
    float4 pa1 = *(const float4*)(Ag + off64);
    float4 pb0 = *(const float4*)(Bg);
    float4 pb1 = *(const float4*)(Bg + off64);

    float acc[4][4][4];  // [m-subtile][n-subtile][frag]
#pragma unroll
    for (int i = 0; i < 4; ++i)
#pragma unroll
        for (int j = 0; j < 4; ++j)
#pragma unroll
            for (int r = 0; r < 4; ++r) acc[i][j][r] = 0.f;

    const int nk = K >> 4;
    for (int kt = 0; kt < nk; ++kt) {
        // store current tile to smem, converting fp32 -> tf32 (RN) once here
        {
            uint4 u;
            u.x = f2tf32(pa0.x); u.y = f2tf32(pa0.y); u.z = f2tf32(pa0.z); u.w = f2tf32(pa0.w);
            *(uint4*)&As[lr][lc] = u;
            u.x = f2tf32(pa1.x); u.y = f2tf32(pa1.y); u.z = f2tf32(pa1.z); u.w = f2tf32(pa1.w);
            *(uint4*)&As[lr + 64][lc] = u;
            u.x = f2tf32(pb0.x); u.y = f2tf32(pb0.y); u.z = f2tf32(pb0.z); u.w = f2tf32(pb0.w);
            *(uint4*)&Bs[lr][lc] = u;
            u.x = f2tf32(pb1.x); u.y = f2tf32(pb1.y); u.z = f2tf32(pb1.z); u.w = f2tf32(pb1.w);
            *(uint4*)&Bs[lr + 64][lc] = u;
        }
        __syncthreads();

        if (kt + 1 < nk) {  // prefetch next gmem tile into registers
            const float* An = Ag + (size_t)(kt + 1) * 16;
            const float* Bn = Bg + (size_t)(kt + 1) * 16;
            pa0 = *(const float4*)(An);
            pa1 = *(const float4*)(An + off64);
            pb0 = *(const float4*)(Bn);
            pb1 = *(const float4*)(Bn + off64);
        }

#pragma unroll
        for (int kk = 0; kk < 16; kk += 8) {
            uint32_t af[4][4], bf[4][2];
#pragma unroll
            for (int mt = 0; mt < 4; ++mt) {
                const int r = wm + mt * 16 + qr;
                af[mt][0] = As[r][kk + qc];
                af[mt][1] = As[r + 8][kk + qc];
                af[mt][2] = As[r][kk + qc + 4];
                af[mt][3] = As[r + 8][kk + qc + 4];
            }
#pragma unroll
            for (int nt = 0; nt < 4; ++nt) {
                const int r = wn + nt * 8 + qr;
                bf[nt][0] = Bs[r][kk + qc];
                bf[nt][1] = Bs[r][kk + qc + 4];
            }
#pragma unroll
            for (int mt = 0; mt < 4; ++mt)
#pragma unroll
                for (int nt = 0; nt < 4; ++nt)
                    mma_tf32(acc[mt][nt], af[mt], bf[nt]);
        }
        __syncthreads();
    }

    // epilogue: add bias, store (float2 per fragment half)
#pragma unroll
    for (int nt = 0; nt < 4; ++nt) {
        const int col = n0 + wn + nt * 8 + qc * 2;
        const float b0 = bias[col], b1 = bias[col + 1];
#pragma unroll
        for (int mt = 0; mt < 4; ++mt) {
            const int row = m0 + wm + mt * 16 + qr;
            float2 o;
            o.x = acc[mt][nt][0] + b0; o.y = acc[mt][nt][1] + b1;
            *(float2*)(C + (size_t)row * N + col) = o;
            o.x = acc[mt][nt][2] + b0; o.y = acc[mt][nt][3] + b1;
            *(float2*)(C + (size_t)(row + 8) * N + col) = o;
        }
    }
}

// ---------------- windowed attention: one block per (window b, head h) ----------------
__global__ __launch_bounds__(192)
void attn_kernel(const float* __restrict__ qkv, const float* __restrict__ bx,
                 float* __restrict__ out)
{
    const int h   = blockIdx.x;
    const int b   = blockIdx.y;
    const int tid = threadIdx.x;

    __shared__ float qt[32][52];   // qt[d][i], cols 49..51 zero-padded
    __shared__ float kt[32][52];   // kt[d][j], cols 49..51 zero-padded
    __shared__ float vs[49][32];   // v[j][d]
    __shared__ float Ps[52][53];   // S / P

    const size_t base = (size_t)b * TOK * QKVN + (size_t)h * HD;

    if (tid < 96) {
        int d = tid / 3, c = 49 + tid % 3;
        qt[d][c] = 0.f; kt[d][c] = 0.f;
    }
    for (int e = tid; e < 392; e += 192) {
        int n = e >> 3, d4 = (e & 7) << 2;
        const float* p = qkv + base + (size_t)n * QKVN + d4;
        float4 q4 = *(const float4*)(p);
        float4 k4 = *(const float4*)(p + DM);
        float4 v4 = *(const float4*)(p + 2 * DM);
        qt[d4 + 0][n] = q4.x; qt[d4 + 1][n] = q4.y;
        qt[d4 + 2][n] = q4.z; qt[d4 + 3][n] = q4.w;
        kt[d4 + 0][n] = k4.x; kt[d4 + 1][n] = k4.y;
        kt[d4 + 2][n] = k4.z; kt[d4 + 3][n] = k4.w;
        *(float4*)&vs[n][d4] = v4;
    }
    __syncthreads();

    if (tid < 169) {
        const int ti = tid % 13, tj = tid / 13;
        const int i0 = ti * 4, j0 = tj * 4;
        float acc[4][4] = {};
#pragma unroll 8
        for (int d = 0; d < 32; ++d) {
            float4 a = *(const float4*)&qt[d][i0];
            float4 c = *(const float4*)&kt[d][j0];
            float av[4] = {a.x, a.y, a.z, a.w};
            float cv[4] = {c.x, c.y, c.z, c.w};
#pragma unroll
            for (int r = 0; r < 4; ++r)
#pragma unroll
                for (int s = 0; s < 4; ++s) acc[r][s] += av[r] * cv[s];
        }
        const float scale = 0.17677669529663687f;  // 32^-0.5
        const float* bh = bx + h * (TOK * TOK);
#pragma unroll
        for (int r = 0; r < 4; ++r)
#pragma unroll
            for (int s = 0; s < 4; ++s) {
                int i = i0 + r, j = j0 + s;
                float v = 0.f;
                if (i < TOK && j < TOK) v = acc[r][s] * scale + bh[i * TOK + j];
                Ps[i][j] = v;
            }
    }
    __syncthreads();

    if (tid < TOK) {
        float mx = -1e30f;
        for (int j = 0; j < TOK; ++j) mx = fmaxf(mx, Ps[tid][j]);
        float s = 0.f;
        for (int j = 0; j < TOK; ++j) {
            float e = __expf(Ps[tid][j] - mx);
            Ps[tid][j] = e; s += e;
        }
        float inv = 1.f / s;
        for (int j = 0; j < TOK; ++j) Ps[tid][j] *= inv;
    }
    __syncthreads();

    if (tid < 104) {
        const int ti = tid % 13, td = tid / 13;
        const int i0 = ti * 4, d0 = td * 4;
        float acc[4][4] = {};
        for (int j = 0; j < TOK; ++j) {
            float4 vv = *(const float4*)&vs[j][d0];
            float p0 = Ps[i0 + 0][j], p1 = Ps[i0 + 1][j];
            float p2 = Ps[i0 + 2][j], p3 = Ps[i0 + 3][j];
            acc[0][0] += p0 * vv.x; acc[0][1] += p0 * vv.y; acc[0][2] += p0 * vv.z; acc[0][3] += p0 * vv.w;
            acc[1][0] += p1 * vv.x; acc[1][1] += p1 * vv.y; acc[1][2] += p1 * vv.z; acc[1][3] += p1 * vv.w;
            acc[2][0] += p2 * vv.x; acc[2][1] += p2 * vv.y; acc[2][2] += p2 * vv.z; acc[2][3] += p2 * vv.w;
            acc[3][0] += p3 * vv.x; acc[3][1] += p3 * vv.y; acc[3][2] += p3 * vv.z; acc[3][3] += p3 * vv.w;
        }
#pragma unroll
        for (int r = 0; r < 4; ++r) {
            int i = i0 + r;
            if (i < TOK) {
                float4 o = {acc[r][0], acc[r][1], acc[r][2], acc[r][3]};
                *(float4*)(out + ((size_t)b * TOK + i) * DM + h * HD + d0) = o;
            }
        }
    }
}

// ---------------- launch ----------------
extern "C" void kernel_launch(void* const* d_in, const int* in_sizes, int n_in,
                              void* d_out, int out_size)
{
    const float* x  = (const float*)d_in[0];
    const float* qw = (const float*)d_in[1];
    const float* qb = (const float*)d_in[2];
    const float* pw = (const float*)d_in[3];
    const float* pb = (const float*)d_in[4];
    const float* bt = (const float*)d_in[5];
    const int*   ri = (const int*)d_in[6];
    float* out = (float*)d_out;

    float *qkv, *att, *bx;
    cudaGetSymbolAddress((void**)&qkv, g_qkv);
    cudaGetSymbolAddress((void**)&att, g_att);
    cudaGetSymbolAddress((void**)&bx,  g_bias);

    // 1) expand relative-position bias to (H, 49, 49)
    bias_expand<<<(NH * TOK * TOK + 255) / 256, 256>>>(bt, ri, bx);

    // 2) QKV projection (TF32 tensor cores): (200704,384) x (1152,384)^T
    gemm_tf32_nt_bias<<<dim3(QKVN / 128, MT / 128), 256>>>(x, qw, qb, qkv, QKVN, DM);

    // 3) windowed attention per (head, window)
    attn_kernel<<<dim3(NH, NWIN), 192>>>(qkv, bx, att);

    // 4) output projection (TF32 tensor cores): (200704,384) x (384,384)^T
    gemm_tf32_nt_bias<<<dim3(DM / 128, MT / 128), 256>>>(att, pw, pb, out, DM, DM);
}